// round 2
// baseline (speedup 1.0000x reference)
#include <cuda_runtime.h>
#include <cuda_bf16.h>

// BalancedBCE: one fused pass computing per-batch partial sums of
//   S_pos[b] = sum of bce where t==1,  S_neg[b] = sum where t==0,  C[b] = #positives
// then a tiny epilogue:
//   loss = sum_b (1 - C_b/N) * S_pos[b] / sum_b C_b
//        + sum_b (    C_b/N) * S_neg[b] / sum_b (N - C_b)

#define BATCH   64
#define BPB     32      // blocks per batch sample
#define THREADS 256

// deterministic scratch: each block writes exactly one slot per quantity
// layout: [0 .. B*BPB) = S_pos partials, [B*BPB .. 2*B*BPB) = S_neg, [2.. ) = counts
__device__ float g_part[3 * BATCH * BPB];

__device__ __forceinline__ void block_reduce3(float& a, float& b, float& c) {
    // warp-level
    #pragma unroll
    for (int off = 16; off > 0; off >>= 1) {
        a += __shfl_down_sync(0xFFFFFFFFu, a, off);
        b += __shfl_down_sync(0xFFFFFFFFu, b, off);
        c += __shfl_down_sync(0xFFFFFFFFu, c, off);
    }
    __shared__ float sa[THREADS / 32], sb[THREADS / 32], sc[THREADS / 32];
    int lane = threadIdx.x & 31;
    int warp = threadIdx.x >> 5;
    if (lane == 0) { sa[warp] = a; sb[warp] = b; sc[warp] = c; }
    __syncthreads();
    if (warp == 0) {
        a = (lane < THREADS / 32) ? sa[lane] : 0.0f;
        b = (lane < THREADS / 32) ? sb[lane] : 0.0f;
        c = (lane < THREADS / 32) ? sc[lane] : 0.0f;
        #pragma unroll
        for (int off = (THREADS / 64); off > 0; off >>= 1) {
            a += __shfl_down_sync(0xFFFFFFFFu, a, off);
            b += __shfl_down_sync(0xFFFFFFFFu, b, off);
            c += __shfl_down_sync(0xFFFFFFFFu, c, off);
        }
    }
}

__global__ void __launch_bounds__(THREADS)
bce_partial_kernel(const float* __restrict__ x_all,
                   const float* __restrict__ t_all,
                   int n_per_sample)
{
    const int b   = blockIdx.y;         // batch sample
    const int blk = blockIdx.x;         // block within sample

    const float4* __restrict__ x4 =
        reinterpret_cast<const float4*>(x_all + (size_t)b * n_per_sample);
    const float4* __restrict__ t4 =
        reinterpret_cast<const float4*>(t_all + (size_t)b * n_per_sample);
    const int n4 = n_per_sample >> 2;

    float sp = 0.0f, sn = 0.0f, cnt = 0.0f;

    for (int i = blk * THREADS + threadIdx.x; i < n4; i += BPB * THREADS) {
        float4 xv = x4[i];
        float4 tv = t4[i];
        float xs[4] = {xv.x, xv.y, xv.z, xv.w};
        float ts[4] = {tv.x, tv.y, tv.z, tv.w};
        #pragma unroll
        for (int k = 0; k < 4; k++) {
            float x = xs[k];
            float t = ts[k];                 // exactly 0.0 or 1.0
            float ax  = fabsf(x);
            float l   = __logf(1.0f + __expf(-ax));
            float bce = fmaxf(x, 0.0f) - x * t + l;
            sp  = fmaf(t, bce, sp);          // add bce when t==1
            sn  = fmaf(1.0f - t, bce, sn);   // add bce when t==0
            cnt += t;
        }
    }

    block_reduce3(sp, sn, cnt);

    if (threadIdx.x == 0) {
        int p = b * BPB + blk;
        g_part[0 * BATCH * BPB + p] = sp;
        g_part[1 * BATCH * BPB + p] = sn;
        g_part[2 * BATCH * BPB + p] = cnt;
    }
}

__global__ void __launch_bounds__(64)
bce_final_kernel(float* __restrict__ out, float n_per_sample)
{
    const int b = threadIdx.x;          // 64 threads, one per batch sample
    float sp = 0.0f, sn = 0.0f, c = 0.0f;
    #pragma unroll 8
    for (int j = 0; j < BPB; j++) {
        sp += g_part[0 * BATCH * BPB + b * BPB + j];
        sn += g_part[1 * BATCH * BPB + b * BPB + j];
        c  += g_part[2 * BATCH * BPB + b * BPB + j];
    }
    float tmean   = c / n_per_sample;
    float wpos    = (1.0f - tmean) * sp;   // beta_pos * S_pos
    float wneg    = tmean * sn;            // beta_neg * S_neg
    float cntpos  = c;
    float cntneg  = n_per_sample - c;

    // reduce 4 values across 64 threads (2 warps) via shared
    __shared__ float s0[2], s1[2], s2[2], s3[2];
    #pragma unroll
    for (int off = 16; off > 0; off >>= 1) {
        wpos   += __shfl_down_sync(0xFFFFFFFFu, wpos,   off);
        wneg   += __shfl_down_sync(0xFFFFFFFFu, wneg,   off);
        cntpos += __shfl_down_sync(0xFFFFFFFFu, cntpos, off);
        cntneg += __shfl_down_sync(0xFFFFFFFFu, cntneg, off);
    }
    int lane = threadIdx.x & 31;
    int warp = threadIdx.x >> 5;
    if (lane == 0) { s0[warp] = wpos; s1[warp] = wneg; s2[warp] = cntpos; s3[warp] = cntneg; }
    __syncthreads();
    if (threadIdx.x == 0) {
        float WP = s0[0] + s0[1];
        float WN = s1[0] + s1[1];
        float CP = s2[0] + s2[1];
        float CN = s3[0] + s3[1];
        out[0] = WP / CP + WN / CN;
    }
}

extern "C" void kernel_launch(void* const* d_in, const int* in_sizes, int n_in,
                              void* d_out, int out_size) {
    const float* x = (const float*)d_in[0];   // logits
    const float* t = (const float*)d_in[1];   // targets (0/1)
    float* out = (float*)d_out;

    const int total = in_sizes[0];
    const int n_per_sample = total / BATCH;   // 262144 for [64,1,512,512]

    dim3 grid(BPB, BATCH);
    bce_partial_kernel<<<grid, THREADS>>>(x, t, n_per_sample);
    bce_final_kernel<<<1, 64>>>(out, (float)n_per_sample);
}